// round 16
// baseline (speedup 1.0000x reference)
#include <cuda_runtime.h>
#include <cuda_bf16.h>
#include <cstdint>

#define BQ 8
#define TT 1024
#define CC 768
#define HH 12
#define DD 64
#define MR (BQ*TT)
#define N3 (3*CC)

// Scratch (allocation-free rule: __device__ globals)
__device__ __align__(16) __nv_bfloat16 g_xh[(size_t)MR*CC], g_xl[(size_t)MR*CC];
__device__ __align__(16) __nv_bfloat16 g_wth[(size_t)N3*CC], g_wtl[(size_t)N3*CC];
__device__ __align__(16) __nv_bfloat16 g_pth[(size_t)CC*CC], g_ptl[(size_t)CC*CC];
__device__ __align__(16) __nv_bfloat16 g_qh[(size_t)BQ*HH*TT*DD], g_ql[(size_t)BQ*HH*TT*DD];
__device__ __align__(16) __nv_bfloat16 g_kh[(size_t)BQ*HH*TT*DD], g_kl[(size_t)BQ*HH*TT*DD];
__device__ __align__(16) float g_v[(size_t)BQ*HH*TT*DD];
__device__ __align__(16) __nv_bfloat16 g_yh[(size_t)MR*CC], g_yl[(size_t)MR*CC];

// ---------------------------------------------------------------------------
// helpers
// ---------------------------------------------------------------------------
__device__ __forceinline__ void mma16816(float* d, const uint32_t* a, const uint32_t* b) {
    asm volatile(
        "mma.sync.aligned.m16n8k16.row.col.f32.bf16.bf16.f32 "
        "{%0,%1,%2,%3}, {%4,%5,%6,%7}, {%8,%9}, {%0,%1,%2,%3};\n"
        : "+f"(d[0]), "+f"(d[1]), "+f"(d[2]), "+f"(d[3])
        : "r"(a[0]), "r"(a[1]), "r"(a[2]), "r"(a[3]), "r"(b[0]), "r"(b[1]));
}

struct __align__(8) BF4 { __nv_bfloat16 a, b, c, d; };

__device__ __forceinline__ void cvt_split(float x, __nv_bfloat16& h, __nv_bfloat16& l) {
    h = __float2bfloat16(x);
    l = __float2bfloat16(x - __bfloat162float(h));
}

__device__ __forceinline__ void cp16(uint32_t saddr, const void* g) {
    asm volatile("cp.async.cg.shared.global [%0], [%1], 16;" :: "r"(saddr), "l"(g));
}
#define CP_COMMIT() asm volatile("cp.async.commit_group;" ::: "memory")
#define CP_WAIT1()  asm volatile("cp.async.wait_group 1;" ::: "memory")

// fast 2^y for y <= 0, FMA-pipe only. ~1.5e-5 max rel error.
__device__ __forceinline__ float exp2p(float y) {
    y = fmaxf(y, -126.f);
    float fi = floorf(y);
    float f = y - fi;
    float p = 1.f + f * (0.6931472f + f * (0.2402265f + f * (0.0555041f +
              f * (0.0096181f + f * (0.0013334f + f * 0.0001546f)))));
    return __int_as_float(__float_as_int(p) + ((int)fi << 23));
}
#define LOG2E 1.4426950408889634f

// ---------------------------------------------------------------------------
// Split X elementwise: fp32 -> bf16 hi/lo
// ---------------------------------------------------------------------------
__global__ void split_x_kernel(const float* __restrict__ x) {
    const size_t i = ((size_t)blockIdx.x * 256 + threadIdx.x) * 4;
    float4 v = *(const float4*)(x + i);
    BF4 h, l;
    cvt_split(v.x, h.a, l.a);
    cvt_split(v.y, h.b, l.b);
    cvt_split(v.z, h.c, l.c);
    cvt_split(v.w, h.d, l.d);
    *(BF4*)&g_xh[i] = h;
    *(BF4*)&g_xl[i] = l;
}

// ---------------------------------------------------------------------------
// Transpose + split: W [768][N] fp32 -> [N][768] bf16 hi/lo.
// ---------------------------------------------------------------------------
__global__ void tsplit_kernel(const float* __restrict__ W, int N, int which) {
    __nv_bfloat16* outh = (which == 0) ? g_wth : g_pth;
    __nv_bfloat16* outl = (which == 0) ? g_wtl : g_ptl;
    __shared__ float t[32][33];
    const int n0 = blockIdx.x * 32, k0 = blockIdx.y * 32;
    const int tx = threadIdx.x & 31, ty = threadIdx.x >> 5;
#pragma unroll
    for (int i = 0; i < 4; i++)
        t[ty + i * 8][tx] = W[(size_t)(k0 + ty + i * 8) * N + n0 + tx];
    __syncthreads();
#pragma unroll
    for (int i = 0; i < 4; i++) {
        float v = t[tx][ty + i * 8];
        __nv_bfloat16 h, l;
        cvt_split(v, h, l);
        const size_t o = (size_t)(n0 + ty + i * 8) * CC + k0 + tx;
        outh[o] = h;
        outl[o] = l;
    }
}

// ---------------------------------------------------------------------------
// QKV HMMA GEMM (R13-proven): BM=128, BN=256, BK=32; 512 thr = 16 warps.
// ---------------------------------------------------------------------------
#define PAD 40
#define A_MAT (128 * PAD)
#define B_MAT (256 * PAD)
#define ST_ELEMS (2 * A_MAT + 2 * B_MAT)
#define OFF_AL A_MAT
#define OFF_BH (2 * A_MAT)
#define OFF_BL (2 * A_MAT + B_MAT)
#define N_STAGE 3
#define GEMM_SMEM (N_STAGE * ST_ELEMS * 2)

__global__ __launch_bounds__(512, 1) void tc_gemm_kernel(
    const float* __restrict__ bias, const float* __restrict__ rel)
{
    extern __shared__ __nv_bfloat16 sm[];
    const uint32_t sbase = (uint32_t)__cvta_generic_to_shared(sm);

    const int tid = threadIdx.x;
    const int wid = tid >> 5, lane = tid & 31;
    const int n0 = blockIdx.x * 256;
    const int m0 = blockIdx.y * 128;

    const int warp_m = wid & 3;
    const int warp_n = wid >> 2;
    const int lr = lane >> 2;
    const int lc = lane & 3;

    const int arowA = tid >> 2;
    const int akoA = (tid & 3) * 8;
    const uint32_t soffA = (uint32_t)(arowA * PAD + akoA) * 2;
    const __nv_bfloat16* gAh = g_xh + (size_t)(m0 + arowA) * CC + akoA;
    const __nv_bfloat16* gAl = g_xl + (size_t)(m0 + arowA) * CC + akoA;
    const int browB = tid >> 1;
    const int bkoB = (tid & 1) * 16;
    const uint32_t soffB = (uint32_t)(browB * PAD + bkoB) * 2;
    const __nv_bfloat16* gBh = g_wth + (size_t)(n0 + browB) * CC + bkoB;
    const __nv_bfloat16* gBl = g_wtl + (size_t)(n0 + browB) * CC + bkoB;

    auto stage_copy = [&](int buf, int k0) {
        const uint32_t sa = sbase + (uint32_t)buf * (ST_ELEMS * 2);
        cp16(sa + soffA, gAh + k0);
        cp16(sa + OFF_AL * 2 + soffA, gAl + k0);
        cp16(sa + OFF_BH * 2 + soffB, gBh + k0);
        cp16(sa + OFF_BH * 2 + soffB + 16, gBh + k0 + 8);
        cp16(sa + OFF_BL * 2 + soffB, gBl + k0);
        cp16(sa + OFF_BL * 2 + soffB + 16, gBl + k0 + 8);
    };

    float acc[2][8][4];
#pragma unroll
    for (int i = 0; i < 2; i++)
#pragma unroll
        for (int j = 0; j < 8; j++)
#pragma unroll
            for (int r = 0; r < 4; r++) acc[i][j][r] = 0.f;

    stage_copy(0, 0);
    CP_COMMIT();
    stage_copy(1, 32);
    CP_COMMIT();

    const int arow0 = warp_m * 32 + lr;
    const int brow0 = warp_n * 64 + lr;
    const int kcol0 = lc * 2;

    for (int s = 0; s < 24; s++) {
        CP_WAIT1();
        __syncthreads();

        const __nv_bfloat16* base = sm + (s % 3) * ST_ELEMS;
        const __nv_bfloat16* sAh = base;
        const __nv_bfloat16* sAl = base + OFF_AL;
        const __nv_bfloat16* sBh = base + OFF_BH;
        const __nv_bfloat16* sBl = base + OFF_BL;

#pragma unroll
        for (int ks = 0; ks < 2; ks++) {
            const int kc = ks * 16 + kcol0;
            uint32_t bh[8][2], bl[8][2];
#pragma unroll
            for (int ni = 0; ni < 8; ni++) {
                const int r = brow0 + ni * 8;
                bh[ni][0] = *(const uint32_t*)(sBh + r * PAD + kc);
                bh[ni][1] = *(const uint32_t*)(sBh + r * PAD + kc + 8);
                bl[ni][0] = *(const uint32_t*)(sBl + r * PAD + kc);
                bl[ni][1] = *(const uint32_t*)(sBl + r * PAD + kc + 8);
            }
#pragma unroll
            for (int mi = 0; mi < 2; mi++) {
                const int r = arow0 + mi * 16;
                uint32_t af[4];
                af[0] = *(const uint32_t*)(sAh + r * PAD + kc);
                af[1] = *(const uint32_t*)(sAh + (r + 8) * PAD + kc);
                af[2] = *(const uint32_t*)(sAh + r * PAD + kc + 8);
                af[3] = *(const uint32_t*)(sAh + (r + 8) * PAD + kc + 8);
#pragma unroll
                for (int ni = 0; ni < 8; ni++)
                    mma16816(acc[mi][ni], af, bh[ni]);
#pragma unroll
                for (int ni = 0; ni < 8; ni++)
                    mma16816(acc[mi][ni], af, bl[ni]);
                af[0] = *(const uint32_t*)(sAl + r * PAD + kc);
                af[1] = *(const uint32_t*)(sAl + (r + 8) * PAD + kc);
                af[2] = *(const uint32_t*)(sAl + r * PAD + kc + 8);
                af[3] = *(const uint32_t*)(sAl + (r + 8) * PAD + kc + 8);
#pragma unroll
                for (int ni = 0; ni < 8; ni++)
                    mma16816(acc[mi][ni], af, bh[ni]);
            }
        }

        if (s + 2 < 24) stage_copy((s + 2) % 3, (s + 2) * 32);
        CP_COMMIT();
    }

    const int seg = n0 / CC;

#pragma unroll
    for (int mi = 0; mi < 2; mi++) {
#pragma unroll
        for (int half = 0; half < 2; half++) {
            const int r = m0 + warp_m * 32 + mi * 16 + lr + half * 8;
#pragma unroll
            for (int ni = 0; ni < 8; ni++) {
                const int gc = n0 + warp_n * 64 + ni * 8 + lc * 2;
                float2 v;
                v.x = acc[mi][ni][half * 2 + 0] + bias[gc];
                v.y = acc[mi][ni][half * 2 + 1] + bias[gc + 1];
                const int bb = r >> 10, t = r & 1023;
                const int cl = gc - seg * CC;
                const int h = cl >> 6, d = cl & 63;
                const size_t idx = (((size_t)bb * HH + h) * TT + t) * DD + d;
                if (seg == 0) {
                    v.x *= 0.125f; v.y *= 0.125f;
                    __nv_bfloat16 hx, lx, hy, ly;
                    cvt_split(v.x, hx, lx);
                    cvt_split(v.y, hy, ly);
                    __nv_bfloat162 h2 = {hx, hy}, l2 = {lx, ly};
                    *(__nv_bfloat162*)&g_qh[idx] = h2;
                    *(__nv_bfloat162*)&g_ql[idx] = l2;
                } else if (seg == 1) {
                    if (t > 0) {
                        float2 rv = *(const float2*)&rel[(size_t)(t - 1) * DD + d];
                        v.x += rv.x; v.y += rv.y;
                    }
                    __nv_bfloat16 hx, lx, hy, ly;
                    cvt_split(v.x, hx, lx);
                    cvt_split(v.y, hy, ly);
                    __nv_bfloat162 h2 = {hx, hy}, l2 = {lx, ly};
                    *(__nv_bfloat162*)&g_kh[idx] = h2;
                    *(__nv_bfloat162*)&g_kl[idx] = l2;
                } else {
                    *(float2*)&g_v[idx] = v;
                }
            }
        }
    }
}

// ---------------------------------------------------------------------------
// Proj HMMA GEMM (R14, passing): BM=64, BN=256, 512 thr = 16 warps (2m x 8n).
// ---------------------------------------------------------------------------
#define A_MAT64 (64 * PAD)
#define ST64 (2 * A_MAT64 + 2 * B_MAT)
#define OFF64_AL A_MAT64
#define OFF64_BH (2 * A_MAT64)
#define OFF64_BL (2 * A_MAT64 + B_MAT)
#define GEMM64_SMEM (3 * ST64 * 2)

__global__ __launch_bounds__(512, 1) void tc_gemm64_kernel(
    const float* __restrict__ bias, float* __restrict__ out)
{
    extern __shared__ __nv_bfloat16 sm[];
    const uint32_t sbase = (uint32_t)__cvta_generic_to_shared(sm);

    const int tid = threadIdx.x;
    const int wid = tid >> 5, lane = tid & 31;
    const int n0 = blockIdx.x * 256;
    const int m0 = blockIdx.y * 64;

    const int warp_m = wid & 1;
    const int warp_n = wid >> 1;
    const int lr = lane >> 2;
    const int lc = lane & 3;

    const int asel = tid >> 8;
    const int arowA = (tid & 255) >> 2;
    const int akoA = (tid & 3) * 8;
    const uint32_t soffA = (uint32_t)(arowA * PAD + akoA) * 2 +
                           (uint32_t)asel * (A_MAT64 * 2);
    const __nv_bfloat16* gA = (asel ? g_yl : g_yh) +
                              (size_t)(m0 + arowA) * CC + akoA;
    const int browB = tid >> 1;
    const int bkoB = (tid & 1) * 16;
    const uint32_t soffB = (uint32_t)(browB * PAD + bkoB) * 2;
    const __nv_bfloat16* gBh = g_pth + (size_t)(n0 + browB) * CC + bkoB;
    const __nv_bfloat16* gBl = g_ptl + (size_t)(n0 + browB) * CC + bkoB;

    auto stage_copy = [&](int buf, int k0) {
        const uint32_t sa = sbase + (uint32_t)buf * (ST64 * 2);
        cp16(sa + soffA, gA + k0);
        cp16(sa + OFF64_BH * 2 + soffB, gBh + k0);
        cp16(sa + OFF64_BH * 2 + soffB + 16, gBh + k0 + 8);
        cp16(sa + OFF64_BL * 2 + soffB, gBl + k0);
        cp16(sa + OFF64_BL * 2 + soffB + 16, gBl + k0 + 8);
    };

    float acc[2][4][4];
#pragma unroll
    for (int i = 0; i < 2; i++)
#pragma unroll
        for (int j = 0; j < 4; j++)
#pragma unroll
            for (int r = 0; r < 4; r++) acc[i][j][r] = 0.f;

    stage_copy(0, 0);
    CP_COMMIT();
    stage_copy(1, 32);
    CP_COMMIT();

    const int arow0 = warp_m * 32 + lr;
    const int brow0 = warp_n * 32 + lr;
    const int kcol0 = lc * 2;

    for (int s = 0; s < 24; s++) {
        CP_WAIT1();
        __syncthreads();

        const __nv_bfloat16* base = sm + (s % 3) * ST64;
        const __nv_bfloat16* sAh = base;
        const __nv_bfloat16* sAl = base + OFF64_AL;
        const __nv_bfloat16* sBh = base + OFF64_BH;
        const __nv_bfloat16* sBl = base + OFF64_BL;

#pragma unroll
        for (int ks = 0; ks < 2; ks++) {
            const int kc = ks * 16 + kcol0;
            uint32_t bh[4][2], bl[4][2];
#pragma unroll
            for (int ni = 0; ni < 4; ni++) {
                const int r = brow0 + ni * 8;
                bh[ni][0] = *(const uint32_t*)(sBh + r * PAD + kc);
                bh[ni][1] = *(const uint32_t*)(sBh + r * PAD + kc + 8);
                bl[ni][0] = *(const uint32_t*)(sBl + r * PAD + kc);
                bl[ni][1] = *(const uint32_t*)(sBl + r * PAD + kc + 8);
            }
#pragma unroll
            for (int mi = 0; mi < 2; mi++) {
                const int r = arow0 + mi * 16;
                uint32_t af[4];
                af[0] = *(const uint32_t*)(sAh + r * PAD + kc);
                af[1] = *(const uint32_t*)(sAh + (r + 8) * PAD + kc);
                af[2] = *(const uint32_t*)(sAh + r * PAD + kc + 8);
                af[3] = *(const uint32_t*)(sAh + (r + 8) * PAD + kc + 8);
#pragma unroll
                for (int ni = 0; ni < 4; ni++)
                    mma16816(acc[mi][ni], af, bh[ni]);
#pragma unroll
                for (int ni = 0; ni < 4; ni++)
                    mma16816(acc[mi][ni], af, bl[ni]);
                af[0] = *(const uint32_t*)(sAl + r * PAD + kc);
                af[1] = *(const uint32_t*)(sAl + (r + 8) * PAD + kc);
                af[2] = *(const uint32_t*)(sAl + r * PAD + kc + 8);
                af[3] = *(const uint32_t*)(sAl + (r + 8) * PAD + kc + 8);
#pragma unroll
                for (int ni = 0; ni < 4; ni++)
                    mma16816(acc[mi][ni], af, bh[ni]);
            }
        }

        if (s + 2 < 24) stage_copy((s + 2) % 3, (s + 2) * 32);
        CP_COMMIT();
    }

#pragma unroll
    for (int mi = 0; mi < 2; mi++) {
#pragma unroll
        for (int half = 0; half < 2; half++) {
            const int r = m0 + warp_m * 32 + mi * 16 + lr + half * 8;
#pragma unroll
            for (int ni = 0; ni < 4; ni++) {
                const int gc = n0 + warp_n * 32 + ni * 8 + lc * 2;
                float2 v;
                v.x = acc[mi][ni][half * 2 + 0] + bias[gc];
                v.y = acc[mi][ni][half * 2 + 1] + bias[gc + 1];
                *(float2*)&out[(size_t)r * CC + gc] = v;
            }
        }
    }
}

// ---------------------------------------------------------------------------
// HMMA causal flash attention, BR=128 / BC=64. R16 fixes vs R15:
// (a) __launch_bounds__(256,1): removes the 128-reg cap that forced spills
//     (live set alone is 128 regs); 16 warps/SM, same as the working GEMM.
// (b) MMA loops inverted: k-step t outer, all-8-accumulator fragment loads
//     per t, then 3 sweeps of 8 INDEPENDENT MMAs (chain spacing 1 -> 8).
// ---------------------------------------------------------------------------
#define FPAD 72

struct FlashSmem {
    __nv_bfloat16 Qh[128][FPAD], Ql[128][FPAD];
    __nv_bfloat16 Kh[64][FPAD], Kl[64][FPAD];
    __nv_bfloat16 Vh[64][FPAD], Vl[64][FPAD];
};

__global__ __launch_bounds__(256, 1) void flash_kernel()
{
    extern __shared__ char fsm_raw[];
    FlashSmem* S = reinterpret_cast<FlashSmem*>(fsm_raw);

    const int it = gridDim.x - 1 - blockIdx.x;   // heaviest first
    const int bh = blockIdx.y;
    const size_t hb = (size_t)bh * TT * DD;
    const float* Vg = g_v + hb;

    const int tid = threadIdx.x;
    const int warp = tid >> 5, lane = tid & 31;
    const int lr = lane >> 2, lc = lane & 3;

    // ---- Copy Q tile: 128 rows (pre-split bf16, uint4) ----
    {
        const __nv_bfloat16* qhg = g_qh + hb + (size_t)it * 128 * DD;
        const __nv_bfloat16* qlg = g_ql + hb + (size_t)it * 128 * DD;
#pragma unroll
        for (int b = 0; b < 4; b++) {
            const int idx = tid + b * 256;
            const int row = idx >> 3, c8 = (idx & 7) * 8;
            *(uint4*)&S->Qh[row][c8] = *(const uint4*)(qhg + row * DD + c8);
            *(uint4*)&S->Ql[row][c8] = *(const uint4*)(qlg + row * DD + c8);
        }
    }
    __syncthreads();

    // ---- Q fragments (each warp: rows warp*16..warp*16+15) ----
    uint32_t qh[4][4], ql[4][4];
    const int qr = warp * 16 + lr;
#pragma unroll
    for (int t = 0; t < 4; t++) {
        const int kc = t * 16 + lc * 2;
        qh[t][0] = *(const uint32_t*)&S->Qh[qr][kc];
        qh[t][1] = *(const uint32_t*)&S->Qh[qr + 8][kc];
        qh[t][2] = *(const uint32_t*)&S->Qh[qr][kc + 8];
        qh[t][3] = *(const uint32_t*)&S->Qh[qr + 8][kc + 8];
        ql[t][0] = *(const uint32_t*)&S->Ql[qr][kc];
        ql[t][1] = *(const uint32_t*)&S->Ql[qr + 8][kc];
        ql[t][2] = *(const uint32_t*)&S->Ql[qr][kc + 8];
        ql[t][3] = *(const uint32_t*)&S->Ql[qr + 8][kc + 8];
    }

    float o[8][4];
#pragma unroll
    for (int nt = 0; nt < 8; nt++)
#pragma unroll
        for (int r = 0; r < 4; r++) o[nt][r] = 0.f;
    float m_run[2] = {-1e30f, -1e30f};
    float l_run[2] = {0.f, 0.f};

    const int jt_max = 2 * it + 1;
    for (int jt = 0; jt <= jt_max; jt++) {
        __syncthreads();
        // ---- K copy: 64 rows ----
        {
            const __nv_bfloat16* khg = g_kh + hb + (size_t)jt * 64 * DD;
            const __nv_bfloat16* klg = g_kl + hb + (size_t)jt * 64 * DD;
#pragma unroll
            for (int b = 0; b < 2; b++) {
                const int idx = tid + b * 256;
                const int row = idx >> 3, c8 = (idx & 7) * 8;
                *(uint4*)&S->Kh[row][c8] = *(const uint4*)(khg + row * DD + c8);
                *(uint4*)&S->Kl[row][c8] = *(const uint4*)(klg + row * DD + c8);
            }
        }
        // ---- V load fp32, split + transpose ----
        {
            const int jr = (tid >> 4) * 4, dc = (tid & 15) * 4;
            const float* vp = Vg + (size_t)(jt * 64 + jr) * DD + dc;
            float4 r0 = *(const float4*)(vp);
            float4 r1 = *(const float4*)(vp + DD);
            float4 r2 = *(const float4*)(vp + 2 * DD);
            float4 r3 = *(const float4*)(vp + 3 * DD);
            float col[4][4] = {
                {r0.x, r1.x, r2.x, r3.x},
                {r0.y, r1.y, r2.y, r3.y},
                {r0.z, r1.z, r2.z, r3.z},
                {r0.w, r1.w, r2.w, r3.w}};
#pragma unroll
            for (int j = 0; j < 4; j++) {
                BF4 h, l;
                cvt_split(col[j][0], h.a, l.a);
                cvt_split(col[j][1], h.b, l.b);
                cvt_split(col[j][2], h.c, l.c);
                cvt_split(col[j][3], h.d, l.d);
                *(BF4*)&S->Vh[dc + j][jr] = h;
                *(BF4*)&S->Vl[dc + j][jr] = l;
            }
        }
        __syncthreads();

        // ---- S = Q K^T (3-pass split); t outer for independent MMA sweeps --
        float s[8][4];
#pragma unroll
        for (int nt = 0; nt < 8; nt++)
#pragma unroll
            for (int r = 0; r < 4; r++) s[nt][r] = 0.f;
#pragma unroll
        for (int t = 0; t < 4; t++) {
            const int kc = t * 16 + lc * 2;
            uint32_t bhf[8][2], blf[8][2];
#pragma unroll
            for (int nt = 0; nt < 8; nt++) {
                const int kr = nt * 8 + lr;
                bhf[nt][0] = *(const uint32_t*)&S->Kh[kr][kc];
                bhf[nt][1] = *(const uint32_t*)&S->Kh[kr][kc + 8];
                blf[nt][0] = *(const uint32_t*)&S->Kl[kr][kc];
                blf[nt][1] = *(const uint32_t*)&S->Kl[kr][kc + 8];
            }
#pragma unroll
            for (int nt = 0; nt < 8; nt++)
                mma16816(s[nt], qh[t], bhf[nt]);
#pragma unroll
            for (int nt = 0; nt < 8; nt++)
                mma16816(s[nt], qh[t], blf[nt]);
#pragma unroll
            for (int nt = 0; nt < 8; nt++)
                mma16816(s[nt], ql[t], bhf[nt]);
        }

        // ---- causal mask (global indices; needed only when jt >= 2*it) ----
        if (jt >= 2 * it) {
            const int rowb = it * 128 + warp * 16 + lr;
            const int colb = jt * 64;
#pragma unroll
            for (int nt = 0; nt < 8; nt++) {
#pragma unroll
                for (int r = 0; r < 4; r++) {
                    const int col = colb + nt * 8 + lc * 2 + (r & 1);
                    const int row = rowb + ((r >> 1) * 8);
                    if (col > row) s[nt][r] = -1e30f;
                }
            }
        }

        // ---- row max, quad shuffle reduce ----
        float mnew[2], fscale[2];
#pragma unroll
        for (int h = 0; h < 2; h++) {
            float m = -1e30f;
#pragma unroll
            for (int nt = 0; nt < 8; nt++)
                m = fmaxf(m, fmaxf(s[nt][h * 2], s[nt][h * 2 + 1]));
            m = fmaxf(m, __shfl_xor_sync(0xFFFFFFFF, m, 1));
            m = fmaxf(m, __shfl_xor_sync(0xFFFFFFFF, m, 2));
            mnew[h] = fmaxf(m_run[h], m);
            fscale[h] = exp2p((m_run[h] - mnew[h]) * LOG2E);
            m_run[h] = mnew[h];
        }

        // ---- p = exp(s - m), row sums ----
        float rsum[2] = {0.f, 0.f};
#pragma unroll
        for (int nt = 0; nt < 8; nt++) {
#pragma unroll
            for (int r = 0; r < 4; r++) {
                const int h = r >> 1;
                float p = exp2p((s[nt][r] - mnew[h]) * LOG2E);
                s[nt][r] = p;
                rsum[h] += p;
            }
        }
#pragma unroll
        for (int h = 0; h < 2; h++) {
            rsum[h] += __shfl_xor_sync(0xFFFFFFFF, rsum[h], 1);
            rsum[h] += __shfl_xor_sync(0xFFFFFFFF, rsum[h], 2);
            l_run[h] = l_run[h] * fscale[h] + rsum[h];
        }

        // ---- rescale O ----
#pragma unroll
        for (int nt = 0; nt < 8; nt++) {
#pragma unroll
            for (int r = 0; r < 4; r++) o[nt][r] *= fscale[r >> 1];
        }

        // ---- pack P hi/lo fragments ----
        uint32_t pfh[4][4], pfl[4][4];
#pragma unroll
        for (int t = 0; t < 4; t++) {
            __nv_bfloat16 h00, l00, h01, l01, h10, l10, h11, l11;
            cvt_split(s[2 * t][0], h00, l00);
            cvt_split(s[2 * t][1], h01, l01);
            cvt_split(s[2 * t][2], h10, l10);
            cvt_split(s[2 * t][3], h11, l11);
            __nv_bfloat162 ph0 = {h00, h01}, pl0 = {l00, l01};
            __nv_bfloat162 ph1 = {h10, h11}, pl1 = {l10, l11};
            __nv_bfloat16 h20, l20, h21, l21, h30, l30, h31, l31;
            cvt_split(s[2 * t + 1][0], h20, l20);
            cvt_split(s[2 * t + 1][1], h21, l21);
            cvt_split(s[2 * t + 1][2], h30, l30);
            cvt_split(s[2 * t + 1][3], h31, l31);
            __nv_bfloat162 ph2 = {h20, h21}, pl2 = {l20, l21};
            __nv_bfloat162 ph3 = {h30, h31}, pl3 = {l30, l31};
            pfh[t][0] = *(uint32_t*)&ph0;
            pfh[t][1] = *(uint32_t*)&ph1;
            pfh[t][2] = *(uint32_t*)&ph2;
            pfh[t][3] = *(uint32_t*)&ph3;
            pfl[t][0] = *(uint32_t*)&pl0;
            pfl[t][1] = *(uint32_t*)&pl1;
            pfl[t][2] = *(uint32_t*)&pl2;
            pfl[t][3] = *(uint32_t*)&pl3;
        }

        // ---- O += P V (3-pass split); t outer for independent MMA sweeps --
#pragma unroll
        for (int t = 0; t < 4; t++) {
            const int jc = t * 16 + lc * 2;
            uint32_t bhf[8][2], blf[8][2];
#pragma unroll
            for (int dt = 0; dt < 8; dt++) {
                const int vr = dt * 8 + lr;
                bhf[dt][0] = *(const uint32_t*)&S->Vh[vr][jc];
                bhf[dt][1] = *(const uint32_t*)&S->Vh[vr][jc + 8];
                blf[dt][0] = *(const uint32_t*)&S->Vl[vr][jc];
                blf[dt][1] = *(const uint32_t*)&S->Vl[vr][jc + 8];
            }
#pragma unroll
            for (int dt = 0; dt < 8; dt++)
                mma16816(o[dt], pfh[t], bhf[dt]);
#pragma unroll
            for (int dt = 0; dt < 8; dt++)
                mma16816(o[dt], pfh[t], blf[dt]);
#pragma unroll
            for (int dt = 0; dt < 8; dt++)
                mma16816(o[dt], pfl[t], bhf[dt]);
        }
    }

    // ---- Output: y split bf16 hi/lo ----
    const int hh = bh % HH, bb = bh / HH;
    const float inv0 = 1.0f / l_run[0];
    const float inv1 = 1.0f / l_run[1];
    const int row0 = it * 128 + warp * 16 + lr;
#pragma unroll
    for (int nt = 0; nt < 8; nt++) {
        const int d = nt * 8 + lc * 2;
        const size_t o0 = ((size_t)bb * TT + row0) * CC + hh * DD + d;
        const size_t o1 = o0 + (size_t)8 * CC;
        __nv_bfloat16 hx, lx, hy, ly;
        cvt_split(o[nt][0] * inv0, hx, lx);
        cvt_split(o[nt][1] * inv0, hy, ly);
        __nv_bfloat162 h2 = {hx, hy}, l2 = {lx, ly};
        *(__nv_bfloat162*)&g_yh[o0] = h2;
        *(__nv_bfloat162*)&g_yl[o0] = l2;
        cvt_split(o[nt][2] * inv1, hx, lx);
        cvt_split(o[nt][3] * inv1, hy, ly);
        __nv_bfloat162 h3 = {hx, hy}, l3 = {lx, ly};
        *(__nv_bfloat162*)&g_yh[o1] = h3;
        *(__nv_bfloat162*)&g_yl[o1] = l3;
    }
}

// ---------------------------------------------------------------------------
extern "C" void kernel_launch(void* const* d_in, const int* in_sizes, int n_in,
                              void* d_out, int out_size)
{
    const float* x      = (const float*)d_in[0];
    const float* w_attn = (const float*)d_in[1];
    const float* b_attn = (const float*)d_in[2];
    const float* w_proj = (const float*)d_in[3];
    const float* b_proj = (const float*)d_in[4];
    const float* rel    = (const float*)d_in[5];
    float* out = (float*)d_out;

    cudaFuncSetAttribute(tc_gemm_kernel,
                         cudaFuncAttributeMaxDynamicSharedMemorySize, GEMM_SMEM);
    cudaFuncSetAttribute(tc_gemm64_kernel,
                         cudaFuncAttributeMaxDynamicSharedMemorySize, GEMM64_SMEM);
    cudaFuncSetAttribute(flash_kernel,
                         cudaFuncAttributeMaxDynamicSharedMemorySize,
                         (int)sizeof(FlashSmem));

    split_x_kernel<<<(MR * CC) / (256 * 4), 256>>>(x);
    tsplit_kernel<<<dim3(N3 / 32, CC / 32), 256>>>(w_attn, N3, 0);
    tsplit_kernel<<<dim3(CC / 32, CC / 32), 256>>>(w_proj, CC, 1);
    tc_gemm_kernel<<<dim3(N3 / 256, MR / 128), 512, GEMM_SMEM>>>(b_attn, rel);
    flash_kernel<<<dim3(TT / 128, BQ * HH), 256, sizeof(FlashSmem)>>>();
    tc_gemm64_kernel<<<dim3(CC / 256, MR / 64), 512, GEMM64_SMEM>>>(b_proj, out);
}

// round 17
// speedup vs baseline: 1.0693x; 1.0693x over previous
#include <cuda_runtime.h>
#include <cuda_bf16.h>
#include <cstdint>

#define BQ 8
#define TT 1024
#define CC 768
#define HH 12
#define DD 64
#define MR (BQ*TT)
#define N3 (3*CC)

// Scratch (allocation-free rule: __device__ globals)
__device__ __align__(16) __nv_bfloat16 g_xh[(size_t)MR*CC], g_xl[(size_t)MR*CC];
__device__ __align__(16) __nv_bfloat16 g_wth[(size_t)N3*CC], g_wtl[(size_t)N3*CC];
__device__ __align__(16) __nv_bfloat16 g_pth[(size_t)CC*CC], g_ptl[(size_t)CC*CC];
__device__ __align__(16) __nv_bfloat16 g_qh[(size_t)BQ*HH*TT*DD], g_ql[(size_t)BQ*HH*TT*DD];
__device__ __align__(16) __nv_bfloat16 g_kh[(size_t)BQ*HH*TT*DD], g_kl[(size_t)BQ*HH*TT*DD];
__device__ __align__(16) float g_v[(size_t)BQ*HH*TT*DD];
__device__ __align__(16) __nv_bfloat16 g_vth[(size_t)BQ*HH*DD*TT];  // V^T split hi
__device__ __align__(16) __nv_bfloat16 g_vtl[(size_t)BQ*HH*DD*TT];  // V^T split lo
__device__ __align__(16) __nv_bfloat16 g_yh[(size_t)MR*CC], g_yl[(size_t)MR*CC];

// ---------------------------------------------------------------------------
// helpers
// ---------------------------------------------------------------------------
__device__ __forceinline__ void mma16816(float* d, const uint32_t* a, const uint32_t* b) {
    asm volatile(
        "mma.sync.aligned.m16n8k16.row.col.f32.bf16.bf16.f32 "
        "{%0,%1,%2,%3}, {%4,%5,%6,%7}, {%8,%9}, {%0,%1,%2,%3};\n"
        : "+f"(d[0]), "+f"(d[1]), "+f"(d[2]), "+f"(d[3])
        : "r"(a[0]), "r"(a[1]), "r"(a[2]), "r"(a[3]), "r"(b[0]), "r"(b[1]));
}

struct __align__(8) BF4 { __nv_bfloat16 a, b, c, d; };

__device__ __forceinline__ void cvt_split(float x, __nv_bfloat16& h, __nv_bfloat16& l) {
    h = __float2bfloat16(x);
    l = __float2bfloat16(x - __bfloat162float(h));
}

__device__ __forceinline__ void cp16(uint32_t saddr, const void* g) {
    asm volatile("cp.async.cg.shared.global [%0], [%1], 16;" :: "r"(saddr), "l"(g));
}
#define CP_COMMIT() asm volatile("cp.async.commit_group;" ::: "memory")
#define CP_WAIT1()  asm volatile("cp.async.wait_group 1;" ::: "memory")
#define CP_WAIT0()  asm volatile("cp.async.wait_group 0;" ::: "memory")

// fast 2^y for y <= 0, FMA-pipe only. ~1.5e-5 max rel error.
__device__ __forceinline__ float exp2p(float y) {
    y = fmaxf(y, -126.f);
    float fi = floorf(y);
    float f = y - fi;
    float p = 1.f + f * (0.6931472f + f * (0.2402265f + f * (0.0555041f +
              f * (0.0096181f + f * (0.0013334f + f * 0.0001546f)))));
    return __int_as_float(__float_as_int(p) + ((int)fi << 23));
}
#define LOG2E 1.4426950408889634f

// ---------------------------------------------------------------------------
// Split X elementwise: fp32 -> bf16 hi/lo
// ---------------------------------------------------------------------------
__global__ void split_x_kernel(const float* __restrict__ x) {
    const size_t i = ((size_t)blockIdx.x * 256 + threadIdx.x) * 4;
    float4 v = *(const float4*)(x + i);
    BF4 h, l;
    cvt_split(v.x, h.a, l.a);
    cvt_split(v.y, h.b, l.b);
    cvt_split(v.z, h.c, l.c);
    cvt_split(v.w, h.d, l.d);
    *(BF4*)&g_xh[i] = h;
    *(BF4*)&g_xl[i] = l;
}

// ---------------------------------------------------------------------------
// Transpose + split: W [768][N] fp32 -> [N][768] bf16 hi/lo.
// ---------------------------------------------------------------------------
__global__ void tsplit_kernel(const float* __restrict__ W, int N, int which) {
    __nv_bfloat16* outh = (which == 0) ? g_wth : g_pth;
    __nv_bfloat16* outl = (which == 0) ? g_wtl : g_ptl;
    __shared__ float t[32][33];
    const int n0 = blockIdx.x * 32, k0 = blockIdx.y * 32;
    const int tx = threadIdx.x & 31, ty = threadIdx.x >> 5;
#pragma unroll
    for (int i = 0; i < 4; i++)
        t[ty + i * 8][tx] = W[(size_t)(k0 + ty + i * 8) * N + n0 + tx];
    __syncthreads();
#pragma unroll
    for (int i = 0; i < 4; i++) {
        float v = t[tx][ty + i * 8];
        __nv_bfloat16 h, l;
        cvt_split(v, h, l);
        const size_t o = (size_t)(n0 + ty + i * 8) * CC + k0 + tx;
        outh[o] = h;
        outl[o] = l;
    }
}

// ---------------------------------------------------------------------------
// Transpose + split V: g_v [bh][t][d] fp32 -> g_vth/g_vtl [bh][d][t] bf16.
// Removes per-iteration V conversion/transposition from the flash hot loop.
// ---------------------------------------------------------------------------
__global__ void vtsplit_kernel() {
    __shared__ float t[32][33];
    const int bh = blockIdx.z;
    const int t0 = blockIdx.x * 32, d0 = blockIdx.y * 32;
    const int tx = threadIdx.x & 31, ty = threadIdx.x >> 5;
    const float* src = g_v + ((size_t)bh * TT + t0) * DD + d0;
#pragma unroll
    for (int i = 0; i < 4; i++)
        t[ty + i * 8][tx] = src[(size_t)(ty + i * 8) * DD + tx];
    __syncthreads();
    __nv_bfloat16* oh = g_vth + ((size_t)bh * DD + d0) * TT + t0;
    __nv_bfloat16* ol = g_vtl + ((size_t)bh * DD + d0) * TT + t0;
#pragma unroll
    for (int i = 0; i < 4; i++) {
        float v = t[tx][ty + i * 8];   // t-index = tx, d-index = ty+i*8
        __nv_bfloat16 h, l;
        cvt_split(v, h, l);
        oh[(size_t)(ty + i * 8) * TT + tx] = h;
        ol[(size_t)(ty + i * 8) * TT + tx] = l;
    }
}

// ---------------------------------------------------------------------------
// QKV HMMA GEMM (R13-proven): BM=128, BN=256, BK=32; 512 thr = 16 warps.
// ---------------------------------------------------------------------------
#define PAD 40
#define A_MAT (128 * PAD)
#define B_MAT (256 * PAD)
#define ST_ELEMS (2 * A_MAT + 2 * B_MAT)
#define OFF_AL A_MAT
#define OFF_BH (2 * A_MAT)
#define OFF_BL (2 * A_MAT + B_MAT)
#define N_STAGE 3
#define GEMM_SMEM (N_STAGE * ST_ELEMS * 2)

__global__ __launch_bounds__(512, 1) void tc_gemm_kernel(
    const float* __restrict__ bias, const float* __restrict__ rel)
{
    extern __shared__ __nv_bfloat16 sm[];
    const uint32_t sbase = (uint32_t)__cvta_generic_to_shared(sm);

    const int tid = threadIdx.x;
    const int wid = tid >> 5, lane = tid & 31;
    const int n0 = blockIdx.x * 256;
    const int m0 = blockIdx.y * 128;

    const int warp_m = wid & 3;
    const int warp_n = wid >> 2;
    const int lr = lane >> 2;
    const int lc = lane & 3;

    const int arowA = tid >> 2;
    const int akoA = (tid & 3) * 8;
    const uint32_t soffA = (uint32_t)(arowA * PAD + akoA) * 2;
    const __nv_bfloat16* gAh = g_xh + (size_t)(m0 + arowA) * CC + akoA;
    const __nv_bfloat16* gAl = g_xl + (size_t)(m0 + arowA) * CC + akoA;
    const int browB = tid >> 1;
    const int bkoB = (tid & 1) * 16;
    const uint32_t soffB = (uint32_t)(browB * PAD + bkoB) * 2;
    const __nv_bfloat16* gBh = g_wth + (size_t)(n0 + browB) * CC + bkoB;
    const __nv_bfloat16* gBl = g_wtl + (size_t)(n0 + browB) * CC + bkoB;

    auto stage_copy = [&](int buf, int k0) {
        const uint32_t sa = sbase + (uint32_t)buf * (ST_ELEMS * 2);
        cp16(sa + soffA, gAh + k0);
        cp16(sa + OFF_AL * 2 + soffA, gAl + k0);
        cp16(sa + OFF_BH * 2 + soffB, gBh + k0);
        cp16(sa + OFF_BH * 2 + soffB + 16, gBh + k0 + 8);
        cp16(sa + OFF_BL * 2 + soffB, gBl + k0);
        cp16(sa + OFF_BL * 2 + soffB + 16, gBl + k0 + 8);
    };

    float acc[2][8][4];
#pragma unroll
    for (int i = 0; i < 2; i++)
#pragma unroll
        for (int j = 0; j < 8; j++)
#pragma unroll
            for (int r = 0; r < 4; r++) acc[i][j][r] = 0.f;

    stage_copy(0, 0);
    CP_COMMIT();
    stage_copy(1, 32);
    CP_COMMIT();

    const int arow0 = warp_m * 32 + lr;
    const int brow0 = warp_n * 64 + lr;
    const int kcol0 = lc * 2;

    for (int s = 0; s < 24; s++) {
        CP_WAIT1();
        __syncthreads();

        const __nv_bfloat16* base = sm + (s % 3) * ST_ELEMS;
        const __nv_bfloat16* sAh = base;
        const __nv_bfloat16* sAl = base + OFF_AL;
        const __nv_bfloat16* sBh = base + OFF_BH;
        const __nv_bfloat16* sBl = base + OFF_BL;

#pragma unroll
        for (int ks = 0; ks < 2; ks++) {
            const int kc = ks * 16 + kcol0;
            uint32_t bh[8][2], bl[8][2];
#pragma unroll
            for (int ni = 0; ni < 8; ni++) {
                const int r = brow0 + ni * 8;
                bh[ni][0] = *(const uint32_t*)(sBh + r * PAD + kc);
                bh[ni][1] = *(const uint32_t*)(sBh + r * PAD + kc + 8);
                bl[ni][0] = *(const uint32_t*)(sBl + r * PAD + kc);
                bl[ni][1] = *(const uint32_t*)(sBl + r * PAD + kc + 8);
            }
#pragma unroll
            for (int mi = 0; mi < 2; mi++) {
                const int r = arow0 + mi * 16;
                uint32_t af[4];
                af[0] = *(const uint32_t*)(sAh + r * PAD + kc);
                af[1] = *(const uint32_t*)(sAh + (r + 8) * PAD + kc);
                af[2] = *(const uint32_t*)(sAh + r * PAD + kc + 8);
                af[3] = *(const uint32_t*)(sAh + (r + 8) * PAD + kc + 8);
#pragma unroll
                for (int ni = 0; ni < 8; ni++)
                    mma16816(acc[mi][ni], af, bh[ni]);
#pragma unroll
                for (int ni = 0; ni < 8; ni++)
                    mma16816(acc[mi][ni], af, bl[ni]);
                af[0] = *(const uint32_t*)(sAl + r * PAD + kc);
                af[1] = *(const uint32_t*)(sAl + (r + 8) * PAD + kc);
                af[2] = *(const uint32_t*)(sAl + r * PAD + kc + 8);
                af[3] = *(const uint32_t*)(sAl + (r + 8) * PAD + kc + 8);
#pragma unroll
                for (int ni = 0; ni < 8; ni++)
                    mma16816(acc[mi][ni], af, bh[ni]);
            }
        }

        if (s + 2 < 24) stage_copy((s + 2) % 3, (s + 2) * 32);
        CP_COMMIT();
    }

    const int seg = n0 / CC;

#pragma unroll
    for (int mi = 0; mi < 2; mi++) {
#pragma unroll
        for (int half = 0; half < 2; half++) {
            const int r = m0 + warp_m * 32 + mi * 16 + lr + half * 8;
#pragma unroll
            for (int ni = 0; ni < 8; ni++) {
                const int gc = n0 + warp_n * 64 + ni * 8 + lc * 2;
                float2 v;
                v.x = acc[mi][ni][half * 2 + 0] + bias[gc];
                v.y = acc[mi][ni][half * 2 + 1] + bias[gc + 1];
                const int bb = r >> 10, t = r & 1023;
                const int cl = gc - seg * CC;
                const int h = cl >> 6, d = cl & 63;
                const size_t idx = (((size_t)bb * HH + h) * TT + t) * DD + d;
                if (seg == 0) {
                    v.x *= 0.125f; v.y *= 0.125f;
                    __nv_bfloat16 hx, lx, hy, ly;
                    cvt_split(v.x, hx, lx);
                    cvt_split(v.y, hy, ly);
                    __nv_bfloat162 h2 = {hx, hy}, l2 = {lx, ly};
                    *(__nv_bfloat162*)&g_qh[idx] = h2;
                    *(__nv_bfloat162*)&g_ql[idx] = l2;
                } else if (seg == 1) {
                    if (t > 0) {
                        float2 rv = *(const float2*)&rel[(size_t)(t - 1) * DD + d];
                        v.x += rv.x; v.y += rv.y;
                    }
                    __nv_bfloat16 hx, lx, hy, ly;
                    cvt_split(v.x, hx, lx);
                    cvt_split(v.y, hy, ly);
                    __nv_bfloat162 h2 = {hx, hy}, l2 = {lx, ly};
                    *(__nv_bfloat162*)&g_kh[idx] = h2;
                    *(__nv_bfloat162*)&g_kl[idx] = l2;
                } else {
                    *(float2*)&g_v[idx] = v;
                }
            }
        }
    }
}

// ---------------------------------------------------------------------------
// Proj HMMA GEMM (R14-proven): BM=64, BN=256, 512 thr = 16 warps (2m x 8n).
// ---------------------------------------------------------------------------
#define A_MAT64 (64 * PAD)
#define ST64 (2 * A_MAT64 + 2 * B_MAT)
#define OFF64_AL A_MAT64
#define OFF64_BH (2 * A_MAT64)
#define OFF64_BL (2 * A_MAT64 + B_MAT)
#define GEMM64_SMEM (3 * ST64 * 2)

__global__ __launch_bounds__(512, 1) void tc_gemm64_kernel(
    const float* __restrict__ bias, float* __restrict__ out)
{
    extern __shared__ __nv_bfloat16 sm[];
    const uint32_t sbase = (uint32_t)__cvta_generic_to_shared(sm);

    const int tid = threadIdx.x;
    const int wid = tid >> 5, lane = tid & 31;
    const int n0 = blockIdx.x * 256;
    const int m0 = blockIdx.y * 64;

    const int warp_m = wid & 1;
    const int warp_n = wid >> 1;
    const int lr = lane >> 2;
    const int lc = lane & 3;

    const int asel = tid >> 8;
    const int arowA = (tid & 255) >> 2;
    const int akoA = (tid & 3) * 8;
    const uint32_t soffA = (uint32_t)(arowA * PAD + akoA) * 2 +
                           (uint32_t)asel * (A_MAT64 * 2);
    const __nv_bfloat16* gA = (asel ? g_yl : g_yh) +
                              (size_t)(m0 + arowA) * CC + akoA;
    const int browB = tid >> 1;
    const int bkoB = (tid & 1) * 16;
    const uint32_t soffB = (uint32_t)(browB * PAD + bkoB) * 2;
    const __nv_bfloat16* gBh = g_pth + (size_t)(n0 + browB) * CC + bkoB;
    const __nv_bfloat16* gBl = g_ptl + (size_t)(n0 + browB) * CC + bkoB;

    auto stage_copy = [&](int buf, int k0) {
        const uint32_t sa = sbase + (uint32_t)buf * (ST64 * 2);
        cp16(sa + soffA, gA + k0);
        cp16(sa + OFF64_BH * 2 + soffB, gBh + k0);
        cp16(sa + OFF64_BH * 2 + soffB + 16, gBh + k0 + 8);
        cp16(sa + OFF64_BL * 2 + soffB, gBl + k0);
        cp16(sa + OFF64_BL * 2 + soffB + 16, gBl + k0 + 8);
    };

    float acc[2][4][4];
#pragma unroll
    for (int i = 0; i < 2; i++)
#pragma unroll
        for (int j = 0; j < 4; j++)
#pragma unroll
            for (int r = 0; r < 4; r++) acc[i][j][r] = 0.f;

    stage_copy(0, 0);
    CP_COMMIT();
    stage_copy(1, 32);
    CP_COMMIT();

    const int arow0 = warp_m * 32 + lr;
    const int brow0 = warp_n * 32 + lr;
    const int kcol0 = lc * 2;

    for (int s = 0; s < 24; s++) {
        CP_WAIT1();
        __syncthreads();

        const __nv_bfloat16* base = sm + (s % 3) * ST64;
        const __nv_bfloat16* sAh = base;
        const __nv_bfloat16* sAl = base + OFF64_AL;
        const __nv_bfloat16* sBh = base + OFF64_BH;
        const __nv_bfloat16* sBl = base + OFF64_BL;

#pragma unroll
        for (int ks = 0; ks < 2; ks++) {
            const int kc = ks * 16 + kcol0;
            uint32_t bh[4][2], bl[4][2];
#pragma unroll
            for (int ni = 0; ni < 4; ni++) {
                const int r = brow0 + ni * 8;
                bh[ni][0] = *(const uint32_t*)(sBh + r * PAD + kc);
                bh[ni][1] = *(const uint32_t*)(sBh + r * PAD + kc + 8);
                bl[ni][0] = *(const uint32_t*)(sBl + r * PAD + kc);
                bl[ni][1] = *(const uint32_t*)(sBl + r * PAD + kc + 8);
            }
#pragma unroll
            for (int mi = 0; mi < 2; mi++) {
                const int r = arow0 + mi * 16;
                uint32_t af[4];
                af[0] = *(const uint32_t*)(sAh + r * PAD + kc);
                af[1] = *(const uint32_t*)(sAh + (r + 8) * PAD + kc);
                af[2] = *(const uint32_t*)(sAh + r * PAD + kc + 8);
                af[3] = *(const uint32_t*)(sAh + (r + 8) * PAD + kc + 8);
#pragma unroll
                for (int ni = 0; ni < 4; ni++)
                    mma16816(acc[mi][ni], af, bh[ni]);
#pragma unroll
                for (int ni = 0; ni < 4; ni++)
                    mma16816(acc[mi][ni], af, bl[ni]);
                af[0] = *(const uint32_t*)(sAl + r * PAD + kc);
                af[1] = *(const uint32_t*)(sAl + (r + 8) * PAD + kc);
                af[2] = *(const uint32_t*)(sAl + r * PAD + kc + 8);
                af[3] = *(const uint32_t*)(sAl + (r + 8) * PAD + kc + 8);
#pragma unroll
                for (int ni = 0; ni < 4; ni++)
                    mma16816(acc[mi][ni], af, bh[ni]);
            }
        }

        if (s + 2 < 24) stage_copy((s + 2) % 3, (s + 2) * 32);
        CP_COMMIT();
    }

#pragma unroll
    for (int mi = 0; mi < 2; mi++) {
#pragma unroll
        for (int half = 0; half < 2; half++) {
            const int r = m0 + warp_m * 32 + mi * 16 + lr + half * 8;
#pragma unroll
            for (int ni = 0; ni < 4; ni++) {
                const int gc = n0 + warp_n * 32 + ni * 8 + lc * 2;
                float2 v;
                v.x = acc[mi][ni][half * 2 + 0] + bias[gc];
                v.y = acc[mi][ni][half * 2 + 1] + bias[gc + 1];
                *(float2*)&out[(size_t)r * CC + gc] = v;
            }
        }
    }
}

// ---------------------------------------------------------------------------
// HMMA causal flash attention, BR=128 / BC=64. R17 change: K and pre-split
// pre-transposed V staged via cp.async (2-stage ring, 1 commit + 1 sync per
// iteration) — removes the exposed LDG->STS round trip and all per-iteration
// V conversion work from the hot loop. Compute body identical to R16.
// ---------------------------------------------------------------------------
#define FPAD 72
#define FSTG (64 * FPAD)   // elems per K/V matrix per stage

struct FlashSmem {
    __nv_bfloat16 Qh[128][FPAD], Ql[128][FPAD];
    __nv_bfloat16 Kh[2][64][FPAD], Kl[2][64][FPAD];
    __nv_bfloat16 Vh[2][64][FPAD], Vl[2][64][FPAD];
};

__global__ __launch_bounds__(256, 1) void flash_kernel()
{
    extern __shared__ char fsm_raw[];
    FlashSmem* S = reinterpret_cast<FlashSmem*>(fsm_raw);

    const int it = gridDim.x - 1 - blockIdx.x;   // heaviest first
    const int bh = blockIdx.y;
    const size_t hb = (size_t)bh * TT * DD;
    const size_t hbv = (size_t)bh * DD * TT;

    const int tid = threadIdx.x;
    const int warp = tid >> 5, lane = tid & 31;
    const int lr = lane >> 2, lc = lane & 3;

    // staging mapping: 512 16B-chunks per matrix-pair set; 2 per thread
    const int srow0 = tid >> 3;            // chunk row for b=0 (0..31)
    const int sc8 = (tid & 7) * 8;         // element offset within row

    auto stage_copy = [&](int buf, int jt) {
        const __nv_bfloat16* khg = g_kh + hb + (size_t)jt * 64 * DD;
        const __nv_bfloat16* klg = g_kl + hb + (size_t)jt * 64 * DD;
        const __nv_bfloat16* vhg = g_vth + hbv + (size_t)jt * 64;
        const __nv_bfloat16* vlg = g_vtl + hbv + (size_t)jt * 64;
#pragma unroll
        for (int b = 0; b < 2; b++) {
            const int row = srow0 + b * 32;
            const uint32_t so = (uint32_t)__cvta_generic_to_shared(
                &S->Kh[buf][row][sc8]);
            cp16(so, khg + row * DD + sc8);
            const uint32_t so2 = (uint32_t)__cvta_generic_to_shared(
                &S->Kl[buf][row][sc8]);
            cp16(so2, klg + row * DD + sc8);
            const uint32_t so3 = (uint32_t)__cvta_generic_to_shared(
                &S->Vh[buf][row][sc8]);
            cp16(so3, vhg + (size_t)row * TT + sc8);
            const uint32_t so4 = (uint32_t)__cvta_generic_to_shared(
                &S->Vl[buf][row][sc8]);
            cp16(so4, vlg + (size_t)row * TT + sc8);
        }
    };

    // ---- Copy Q tile: 128 rows (pre-split bf16, uint4) ----
    {
        const __nv_bfloat16* qhg = g_qh + hb + (size_t)it * 128 * DD;
        const __nv_bfloat16* qlg = g_ql + hb + (size_t)it * 128 * DD;
#pragma unroll
        for (int b = 0; b < 4; b++) {
            const int idx = tid + b * 256;
            const int row = idx >> 3, c8 = (idx & 7) * 8;
            *(uint4*)&S->Qh[row][c8] = *(const uint4*)(qhg + row * DD + c8);
            *(uint4*)&S->Ql[row][c8] = *(const uint4*)(qlg + row * DD + c8);
        }
    }
    // prologue: stage 0
    stage_copy(0, 0);
    CP_COMMIT();
    __syncthreads();

    // ---- Q fragments (each warp: rows warp*16..warp*16+15) ----
    uint32_t qh[4][4], ql[4][4];
    const int qr = warp * 16 + lr;
#pragma unroll
    for (int t = 0; t < 4; t++) {
        const int kc = t * 16 + lc * 2;
        qh[t][0] = *(const uint32_t*)&S->Qh[qr][kc];
        qh[t][1] = *(const uint32_t*)&S->Qh[qr + 8][kc];
        qh[t][2] = *(const uint32_t*)&S->Qh[qr][kc + 8];
        qh[t][3] = *(const uint32_t*)&S->Qh[qr + 8][kc + 8];
        ql[t][0] = *(const uint32_t*)&S->Ql[qr][kc];
        ql[t][1] = *(const uint32_t*)&S->Ql[qr + 8][kc];
        ql[t][2] = *(const uint32_t*)&S->Ql[qr][kc + 8];
        ql[t][3] = *(const uint32_t*)&S->Ql[qr + 8][kc + 8];
    }

    float o[8][4];
#pragma unroll
    for (int nt = 0; nt < 8; nt++)
#pragma unroll
        for (int r = 0; r < 4; r++) o[nt][r] = 0.f;
    float m_run[2] = {-1e30f, -1e30f};
    float l_run[2] = {0.f, 0.f};

    const int jt_max = 2 * it + 1;
    for (int jt = 0; jt <= jt_max; jt++) {
        CP_WAIT0();
        __syncthreads();   // stage jt ready; all warps done with stage jt-1
        if (jt < jt_max) {
            stage_copy((jt + 1) & 1, jt + 1);
            CP_COMMIT();
        }
        const int cur = jt & 1;

        // ---- S = Q K^T (3-pass split); t outer for independent MMA sweeps --
        float s[8][4];
#pragma unroll
        for (int nt = 0; nt < 8; nt++)
#pragma unroll
            for (int r = 0; r < 4; r++) s[nt][r] = 0.f;
#pragma unroll
        for (int t = 0; t < 4; t++) {
            const int kc = t * 16 + lc * 2;
            uint32_t bhf[8][2], blf[8][2];
#pragma unroll
            for (int nt = 0; nt < 8; nt++) {
                const int kr = nt * 8 + lr;
                bhf[nt][0] = *(const uint32_t*)&S->Kh[cur][kr][kc];
                bhf[nt][1] = *(const uint32_t*)&S->Kh[cur][kr][kc + 8];
                blf[nt][0] = *(const uint32_t*)&S->Kl[cur][kr][kc];
                blf[nt][1] = *(const uint32_t*)&S->Kl[cur][kr][kc + 8];
            }
#pragma unroll
            for (int nt = 0; nt < 8; nt++)
                mma16816(s[nt], qh[t], bhf[nt]);
#pragma unroll
            for (int nt = 0; nt < 8; nt++)
                mma16816(s[nt], qh[t], blf[nt]);
#pragma unroll
            for (int nt = 0; nt < 8; nt++)
                mma16816(s[nt], ql[t], bhf[nt]);
        }

        // ---- causal mask (global indices; needed only when jt >= 2*it) ----
        if (jt >= 2 * it) {
            const int rowb = it * 128 + warp * 16 + lr;
            const int colb = jt * 64;
#pragma unroll
            for (int nt = 0; nt < 8; nt++) {
#pragma unroll
                for (int r = 0; r < 4; r++) {
                    const int col = colb + nt * 8 + lc * 2 + (r & 1);
                    const int row = rowb + ((r >> 1) * 8);
                    if (col > row) s[nt][r] = -1e30f;
                }
            }
        }

        // ---- row max, quad shuffle reduce ----
        float mnew[2], fscale[2];
#pragma unroll
        for (int h = 0; h < 2; h++) {
            float m = -1e30f;
#pragma unroll
            for (int nt = 0; nt < 8; nt++)
                m = fmaxf(m, fmaxf(s[nt][h * 2], s[nt][h * 2 + 1]));
            m = fmaxf(m, __shfl_xor_sync(0xFFFFFFFF, m, 1));
            m = fmaxf(m, __shfl_xor_sync(0xFFFFFFFF, m, 2));
            mnew[h] = fmaxf(m_run[h], m);
            fscale[h] = exp2p((m_run[h] - mnew[h]) * LOG2E);
            m_run[h] = mnew[h];
        }

        // ---- p = exp(s - m), row sums ----
        float rsum[2] = {0.f, 0.f};
#pragma unroll
        for (int nt = 0; nt < 8; nt++) {
#pragma unroll
            for (int r = 0; r < 4; r++) {
                const int h = r >> 1;
                float p = exp2p((s[nt][r] - mnew[h]) * LOG2E);
                s[nt][r] = p;
                rsum[h] += p;
            }
        }
#pragma unroll
        for (int h = 0; h < 2; h++) {
            rsum[h] += __shfl_xor_sync(0xFFFFFFFF, rsum[h], 1);
            rsum[h] += __shfl_xor_sync(0xFFFFFFFF, rsum[h], 2);
            l_run[h] = l_run[h] * fscale[h] + rsum[h];
        }

        // ---- rescale O ----
#pragma unroll
        for (int nt = 0; nt < 8; nt++) {
#pragma unroll
            for (int r = 0; r < 4; r++) o[nt][r] *= fscale[r >> 1];
        }

        // ---- pack P hi/lo fragments ----
        uint32_t pfh[4][4], pfl[4][4];
#pragma unroll
        for (int t = 0; t < 4; t++) {
            __nv_bfloat16 h00, l00, h01, l01, h10, l10, h11, l11;
            cvt_split(s[2 * t][0], h00, l00);
            cvt_split(s[2 * t][1], h01, l01);
            cvt_split(s[2 * t][2], h10, l10);
            cvt_split(s[2 * t][3], h11, l11);
            __nv_bfloat162 ph0 = {h00, h01}, pl0 = {l00, l01};
            __nv_bfloat162 ph1 = {h10, h11}, pl1 = {l10, l11};
            __nv_bfloat16 h20, l20, h21, l21, h30, l30, h31, l31;
            cvt_split(s[2 * t + 1][0], h20, l20);
            cvt_split(s[2 * t + 1][1], h21, l21);
            cvt_split(s[2 * t + 1][2], h30, l30);
            cvt_split(s[2 * t + 1][3], h31, l31);
            __nv_bfloat162 ph2 = {h20, h21}, pl2 = {l20, l21};
            __nv_bfloat162 ph3 = {h30, h31}, pl3 = {l30, l31};
            pfh[t][0] = *(uint32_t*)&ph0;
            pfh[t][1] = *(uint32_t*)&ph1;
            pfh[t][2] = *(uint32_t*)&ph2;
            pfh[t][3] = *(uint32_t*)&ph3;
            pfl[t][0] = *(uint32_t*)&pl0;
            pfl[t][1] = *(uint32_t*)&pl1;
            pfl[t][2] = *(uint32_t*)&pl2;
            pfl[t][3] = *(uint32_t*)&pl3;
        }

        // ---- O += P V (3-pass split); t outer for independent MMA sweeps --
#pragma unroll
        for (int t = 0; t < 4; t++) {
            const int jc = t * 16 + lc * 2;
            uint32_t bhf[8][2], blf[8][2];
#pragma unroll
            for (int dt = 0; dt < 8; dt++) {
                const int vr = dt * 8 + lr;
                bhf[dt][0] = *(const uint32_t*)&S->Vh[cur][vr][jc];
                bhf[dt][1] = *(const uint32_t*)&S->Vh[cur][vr][jc + 8];
                blf[dt][0] = *(const uint32_t*)&S->Vl[cur][vr][jc];
                blf[dt][1] = *(const uint32_t*)&S->Vl[cur][vr][jc + 8];
            }
#pragma unroll
            for (int dt = 0; dt < 8; dt++)
                mma16816(o[dt], pfh[t], bhf[dt]);
#pragma unroll
            for (int dt = 0; dt < 8; dt++)
                mma16816(o[dt], pfh[t], blf[dt]);
#pragma unroll
            for (int dt = 0; dt < 8; dt++)
                mma16816(o[dt], pfl[t], bhf[dt]);
        }
    }

    // ---- Output: y split bf16 hi/lo ----
    const int hh = bh % HH, bb = bh / HH;
    const float inv0 = 1.0f / l_run[0];
    const float inv1 = 1.0f / l_run[1];
    const int row0 = it * 128 + warp * 16 + lr;
#pragma unroll
    for (int nt = 0; nt < 8; nt++) {
        const int d = nt * 8 + lc * 2;
        const size_t o0 = ((size_t)bb * TT + row0) * CC + hh * DD + d;
        const size_t o1 = o0 + (size_t)8 * CC;
        __nv_bfloat16 hx, lx, hy, ly;
        cvt_split(o[nt][0] * inv0, hx, lx);
        cvt_split(o[nt][1] * inv0, hy, ly);
        __nv_bfloat162 h2 = {hx, hy}, l2 = {lx, ly};
        *(__nv_bfloat162*)&g_yh[o0] = h2;
        *(__nv_bfloat162*)&g_yl[o0] = l2;
        cvt_split(o[nt][2] * inv1, hx, lx);
        cvt_split(o[nt][3] * inv1, hy, ly);
        __nv_bfloat162 h3 = {hx, hy}, l3 = {lx, ly};
        *(__nv_bfloat162*)&g_yh[o1] = h3;
        *(__nv_bfloat162*)&g_yl[o1] = l3;
    }
}

// ---------------------------------------------------------------------------
extern "C" void kernel_launch(void* const* d_in, const int* in_sizes, int n_in,
                              void* d_out, int out_size)
{
    const float* x      = (const float*)d_in[0];
    const float* w_attn = (const float*)d_in[1];
    const float* b_attn = (const float*)d_in[2];
    const float* w_proj = (const float*)d_in[3];
    const float* b_proj = (const float*)d_in[4];
    const float* rel    = (const float*)d_in[5];
    float* out = (float*)d_out;

    cudaFuncSetAttribute(tc_gemm_kernel,
                         cudaFuncAttributeMaxDynamicSharedMemorySize, GEMM_SMEM);
    cudaFuncSetAttribute(tc_gemm64_kernel,
                         cudaFuncAttributeMaxDynamicSharedMemorySize, GEMM64_SMEM);
    cudaFuncSetAttribute(flash_kernel,
                         cudaFuncAttributeMaxDynamicSharedMemorySize,
                         (int)sizeof(FlashSmem));

    split_x_kernel<<<(MR * CC) / (256 * 4), 256>>>(x);
    tsplit_kernel<<<dim3(N3 / 32, CC / 32), 256>>>(w_attn, N3, 0);
    tsplit_kernel<<<dim3(CC / 32, CC / 32), 256>>>(w_proj, CC, 1);
    tc_gemm_kernel<<<dim3(N3 / 256, MR / 128), 512, GEMM_SMEM>>>(b_attn, rel);
    vtsplit_kernel<<<dim3(TT / 32, DD / 32, BQ * HH), 256>>>();
    flash_kernel<<<dim3(TT / 128, BQ * HH), 256, sizeof(FlashSmem)>>>();
    tc_gemm64_kernel<<<dim3(CC / 256, MR / 64), 512, GEMM64_SMEM>>>(b_proj, out);
}